// round 1
// baseline (speedup 1.0000x reference)
#include <cuda_runtime.h>
#include <cuda_bf16.h>
#include <math.h>

// Problem constants
#define BATCH 4
#define SEQ   2048
#define EMB   1024
#define NH    16
#define HD    64          // head dim
#define M_ROWS (BATCH*SEQ)        // 8192
#define QKV_N  (3*EMB)            // 3072

// Scratch (device globals: allocation-free)
__device__ float g_qkv[(size_t)M_ROWS * QKV_N];   // [B*T, 3C]
__device__ float g_y  [(size_t)M_ROWS * EMB];     // [B*T, C]

// ---------------------------------------------------------------------------
// Generic fp32 SIMT GEMM: C = A[MxK] @ B[KxN], row-major, all dims multiple
// of tile sizes. 128x128 tile, BK=16, 256 threads, 8x8 per thread.
// ---------------------------------------------------------------------------
__global__ __launch_bounds__(256) void gemm128(const float* __restrict__ A,
                                               const float* __restrict__ B,
                                               float* __restrict__ C,
                                               int M, int N, int K)
{
    __shared__ float As[16][128];   // transposed: As[k][m]
    __shared__ float Bs[16][128];   // Bs[k][n]

    const int tid = threadIdx.x;
    const int tx = tid & 15;        // 0..15 -> col block
    const int ty = tid >> 4;        // 0..15 -> row block
    const int row0 = blockIdx.y * 128 + ty * 8;
    const int col0 = blockIdx.x * 128 + tx * 8;

    float acc[8][8];
#pragma unroll
    for (int i = 0; i < 8; i++)
#pragma unroll
        for (int j = 0; j < 8; j++) acc[i][j] = 0.f;

    for (int k0 = 0; k0 < K; k0 += 16) {
        // Load A tile (128 x 16) transposed into As
#pragma unroll
        for (int it = 0; it < 2; it++) {
            int idx = tid + it * 256;          // 0..511 float4 slots
            int r   = idx >> 2;                // 0..127 (tile row)
            int cv  = idx & 3;                 // 0..3   (k float4)
            float4 a = *(const float4*)(A + (size_t)(blockIdx.y*128 + r)*K + k0 + cv*4);
            As[cv*4+0][r] = a.x;
            As[cv*4+1][r] = a.y;
            As[cv*4+2][r] = a.z;
            As[cv*4+3][r] = a.w;
        }
        // Load B tile (16 x 128)
#pragma unroll
        for (int it = 0; it < 2; it++) {
            int idx = tid + it * 256;
            int r   = idx >> 5;                // 0..15
            int cv  = idx & 31;                // 0..31
            *(float4*)(&Bs[r][cv*4]) =
                *(const float4*)(B + (size_t)(k0 + r)*N + blockIdx.x*128 + cv*4);
        }
        __syncthreads();

#pragma unroll
        for (int k = 0; k < 16; k++) {
            float a[8], b[8];
            *(float4*)(a)   = *(float4*)(&As[k][ty*8]);
            *(float4*)(a+4) = *(float4*)(&As[k][ty*8+4]);
            *(float4*)(b)   = *(float4*)(&Bs[k][tx*8]);
            *(float4*)(b+4) = *(float4*)(&Bs[k][tx*8+4]);
#pragma unroll
            for (int i = 0; i < 8; i++)
#pragma unroll
                for (int j = 0; j < 8; j++)
                    acc[i][j] = fmaf(a[i], b[j], acc[i][j]);
        }
        __syncthreads();
    }

#pragma unroll
    for (int i = 0; i < 8; i++) {
#pragma unroll
        for (int jv = 0; jv < 2; jv++) {
            float4 v = make_float4(acc[i][jv*4+0], acc[i][jv*4+1],
                                   acc[i][jv*4+2], acc[i][jv*4+3]);
            *(float4*)(C + (size_t)(row0+i)*N + col0 + jv*4) = v;
        }
    }
}

// ---------------------------------------------------------------------------
// Causal flash attention, fp32. One block = (batch b, head h, q-tile of 64).
// BQ=64 queries, BK=32 keys per inner tile, online softmax.
// Thread layout: 256 threads as 16(ty: 4 q-rows each) x 16(tx).
//   S frag:  4 rows x 2 cols (tx*2)      O frag: 4 rows x 4 cols (tx*4)
// ---------------------------------------------------------------------------
#define BQ 64
#define BKK 32
#define NEG_BIG (-1e30f)

__global__ __launch_bounds__(256) void attn_kernel(const float* __restrict__ qkv,
                                                   float* __restrict__ y)
{
    __shared__ float QsT[HD][BQ + 4];    // [d][i]
    __shared__ float KsT[HD][BKK + 4];   // [d][j]
    __shared__ float Vs [BKK][HD];       // [j][d]
    __shared__ float PsT[BKK][BQ + 4];   // [j][i]

    const int tid = threadIdx.x;
    const int tx = tid & 15;
    const int ty = tid >> 4;
    const int i0 = ty * 4;          // q rows of this thread
    const int j0 = tx * 2;          // S cols
    const int d0 = tx * 4;          // O cols

    const int qt = blockIdx.x;      // 0..31
    const int h  = blockIdx.y;
    const int b  = blockIdx.z;

    const size_t rowstride = 3 * EMB;
    const size_t qcol = (size_t)h * HD;
    const size_t kcol = EMB + (size_t)h * HD;
    const size_t vcol = 2 * EMB + (size_t)h * HD;
    const size_t batch_base = (size_t)b * SEQ;

    // Load Q tile transposed: QsT[d][i]
#pragma unroll
    for (int it = 0; it < 4; it++) {
        int idx = tid + it * 256;           // 0..1023 float4 slots
        int tl  = idx >> 4;                 // 0..63 local q row
        int dv  = idx & 15;                 // 0..15
        float4 q = *(const float4*)(qkv + (batch_base + qt*BQ + tl)*rowstride + qcol + dv*4);
        QsT[dv*4+0][tl] = q.x;
        QsT[dv*4+1][tl] = q.y;
        QsT[dv*4+2][tl] = q.z;
        QsT[dv*4+3][tl] = q.w;
    }

    float m[4], l[4], o[4][4];
#pragma unroll
    for (int i = 0; i < 4; i++) {
        m[i] = NEG_BIG; l[i] = 0.f;
#pragma unroll
        for (int d = 0; d < 4; d++) o[i][d] = 0.f;
    }

    const float scale = 0.125f;  // 1/sqrt(64)
    const int n_kt = 2*qt + 2;   // key tiles needed (causal)

    for (int kt = 0; kt < n_kt; kt++) {
        __syncthreads();   // prior P@V readers done with KsT/Vs/PsT
        // Load K tile transposed, V tile direct (each 32x64 = 512 float4)
#pragma unroll
        for (int it = 0; it < 2; it++) {
            int idx = tid + it * 256;       // 0..511
            int tl  = idx >> 4;             // 0..31
            int dv  = idx & 15;             // 0..15
            const float* base = qkv + (batch_base + kt*BKK + tl)*rowstride;
            float4 kk = *(const float4*)(base + kcol + dv*4);
            KsT[dv*4+0][tl] = kk.x;
            KsT[dv*4+1][tl] = kk.y;
            KsT[dv*4+2][tl] = kk.z;
            KsT[dv*4+3][tl] = kk.w;
            *(float4*)(&Vs[tl][dv*4]) = *(const float4*)(base + vcol + dv*4);
        }
        __syncthreads();

        // S = scale * Q @ K^T  (4x2 frag)
        float s[4][2];
#pragma unroll
        for (int i = 0; i < 4; i++) { s[i][0] = 0.f; s[i][1] = 0.f; }
#pragma unroll 8
        for (int d = 0; d < HD; d++) {
            float4 qf = *(float4*)(&QsT[d][i0]);
            float2 kf = *(float2*)(&KsT[d][j0]);
            s[0][0] = fmaf(qf.x, kf.x, s[0][0]); s[0][1] = fmaf(qf.x, kf.y, s[0][1]);
            s[1][0] = fmaf(qf.y, kf.x, s[1][0]); s[1][1] = fmaf(qf.y, kf.y, s[1][1]);
            s[2][0] = fmaf(qf.z, kf.x, s[2][0]); s[2][1] = fmaf(qf.z, kf.y, s[2][1]);
            s[3][0] = fmaf(qf.w, kf.x, s[3][0]); s[3][1] = fmaf(qf.w, kf.y, s[3][1]);
        }

        // scale + causal mask
#pragma unroll
        for (int i = 0; i < 4; i++) {
            int ig = qt*BQ + i0 + i;
#pragma unroll
            for (int j = 0; j < 2; j++) {
                int jg = kt*BKK + j0 + j;
                s[i][j] = (jg <= ig) ? s[i][j] * scale : NEG_BIG;
            }
        }

        // online softmax update (per-row reductions over the 16 tx threads;
        // same-ty threads are a contiguous 16-lane group inside a warp)
        float alpha[4];
#pragma unroll
        for (int i = 0; i < 4; i++) {
            float mx = fmaxf(s[i][0], s[i][1]);
#pragma unroll
            for (int off = 1; off < 16; off <<= 1)
                mx = fmaxf(mx, __shfl_xor_sync(0xffffffffu, mx, off));
            float mn = fmaxf(m[i], mx);
            float p0 = __expf(s[i][0] - mn);
            float p1 = __expf(s[i][1] - mn);
            float rs = p0 + p1;
#pragma unroll
            for (int off = 1; off < 16; off <<= 1)
                rs += __shfl_xor_sync(0xffffffffu, rs, off);
            alpha[i] = __expf(m[i] - mn);
            l[i] = l[i] * alpha[i] + rs;
            m[i] = mn;
            PsT[j0+0][i0+i] = p0;
            PsT[j0+1][i0+i] = p1;
#pragma unroll
            for (int d = 0; d < 4; d++) o[i][d] *= alpha[i];
        }
        __syncthreads();

        // O += P @ V   (4x4 frag over 32 keys)
#pragma unroll 8
        for (int j = 0; j < BKK; j++) {
            float4 pf = *(float4*)(&PsT[j][i0]);
            float4 vf = *(float4*)(&Vs[j][d0]);
            o[0][0] = fmaf(pf.x, vf.x, o[0][0]); o[0][1] = fmaf(pf.x, vf.y, o[0][1]);
            o[0][2] = fmaf(pf.x, vf.z, o[0][2]); o[0][3] = fmaf(pf.x, vf.w, o[0][3]);
            o[1][0] = fmaf(pf.y, vf.x, o[1][0]); o[1][1] = fmaf(pf.y, vf.y, o[1][1]);
            o[1][2] = fmaf(pf.y, vf.z, o[1][2]); o[1][3] = fmaf(pf.y, vf.w, o[1][3]);
            o[2][0] = fmaf(pf.z, vf.x, o[2][0]); o[2][1] = fmaf(pf.z, vf.y, o[2][1]);
            o[2][2] = fmaf(pf.z, vf.z, o[2][2]); o[2][3] = fmaf(pf.z, vf.w, o[2][3]);
            o[3][0] = fmaf(pf.w, vf.x, o[3][0]); o[3][1] = fmaf(pf.w, vf.y, o[3][1]);
            o[3][2] = fmaf(pf.w, vf.z, o[3][2]); o[3][3] = fmaf(pf.w, vf.w, o[3][3]);
        }
    }

    // write y[B*T, C] at col h*64 + d
#pragma unroll
    for (int i = 0; i < 4; i++) {
        float inv = 1.0f / l[i];
        float4 v = make_float4(o[i][0]*inv, o[i][1]*inv, o[i][2]*inv, o[i][3]*inv);
        *(float4*)(y + (batch_base + qt*BQ + i0 + i)*(size_t)EMB + h*HD + d0) = v;
    }
}

// ---------------------------------------------------------------------------
extern "C" void kernel_launch(void* const* d_in, const int* in_sizes, int n_in,
                              void* d_out, int out_size)
{
    const float* x0     = (const float*)d_in[0];   // [4,2048,1024]
    const float* w_attn = (const float*)d_in[1];   // [1024,3072]
    const float* w_proj = (const float*)d_in[2];   // [1024,1024]
    float* out = (float*)d_out;                    // [4,2048,1024]

    void* p_qkv_v = nullptr;
    void* p_y_v   = nullptr;
    cudaGetSymbolAddress(&p_qkv_v, g_qkv);
    cudaGetSymbolAddress(&p_y_v,   g_y);
    float* p_qkv = (float*)p_qkv_v;
    float* p_y   = (float*)p_y_v;

    // 1) qkv = x0 @ w_attn        [8192,1024] x [1024,3072]
    gemm128<<<dim3(QKV_N/128, M_ROWS/128), 256>>>(x0, w_attn, p_qkv,
                                                  M_ROWS, QKV_N, EMB);
    // 2) flash attention          -> y [8192,1024]
    attn_kernel<<<dim3(SEQ/BQ, NH, BATCH), 256>>>(p_qkv, p_y);
    // 3) out = y @ w_proj         [8192,1024] x [1024,1024]
    gemm128<<<dim3(EMB/128, M_ROWS/128), 256>>>(p_y, w_proj, out,
                                                M_ROWS, EMB, EMB);
}

// round 2
// speedup vs baseline: 1.5510x; 1.5510x over previous
#include <cuda_runtime.h>
#include <cuda_bf16.h>
#include <math.h>
#include <stdint.h>

// Problem constants
#define BATCH 4
#define SEQ   2048
#define EMB   1024
#define NH    16
#define HD    64          // head dim
#define M_ROWS (BATCH*SEQ)        // 8192
#define QKV_N  (3*EMB)            // 3072

// Scratch (device globals: allocation-free)
__device__ float g_qkv[(size_t)M_ROWS * QKV_N];   // [B*T, 3C]
__device__ float g_y  [(size_t)M_ROWS * EMB];     // [B*T, C]

__device__ __forceinline__ float f2tf32(float x) {
    float y;
    asm("cvt.rna.tf32.f32 %0, %1;" : "=f"(y) : "f"(x));
    return y;
}
__device__ __forceinline__ uint32_t smem_u32(const void* p) {
    return (uint32_t)__cvta_generic_to_shared(p);
}

// ---------------------------------------------------------------------------
// TF32 tensor-core GEMM: C = A[MxK] @ B[KxN], row-major.
// CTA tile 128x128, BK=16, 256 threads (8 warps, 2x4 grid, warp tile 64x32).
// mma.sync m16n8k8 tf32, fp32 accumulate. Double-buffered smem.
// ---------------------------------------------------------------------------
#define GBK 16

__global__ __launch_bounds__(256) void gemm_tc(const float* __restrict__ A,
                                               const float* __restrict__ B,
                                               float* __restrict__ C,
                                               int M, int N, int K)
{
    __shared__ float As[2][128][20];    // [buf][m][k], +4 pad
    __shared__ float Bs[2][GBK][132];   // [buf][k][n], +4 pad

    const int tid  = threadIdx.x;
    const int lane = tid & 31;
    const int wid  = tid >> 5;
    const int wm   = wid >> 2;          // 0..1
    const int wn   = wid & 3;           // 0..3
    const int m0   = blockIdx.y * 128;
    const int n0   = blockIdx.x * 128;

    // A tile: 128x16 = 512 float4, 2 per thread
    const int ar  = tid >> 2;           // 0..63 (and +64)
    const int ac4 = tid & 3;            // float4 within k-row
    // B tile: 16x128 = 512 float4, 2 per thread
    const int bk  = tid >> 5;           // 0..7 (and +8)
    const int bn4 = tid & 31;

    float acc[4][4][4];
#pragma unroll
    for (int i = 0; i < 4; i++)
#pragma unroll
        for (int j = 0; j < 4; j++)
#pragma unroll
            for (int r = 0; r < 4; r++) acc[i][j][r] = 0.f;

    float4 sa0, sa1, sb0, sb1;

    // ldmatrix source address for A-fragments (per m-tile, per kk below)
    const int lrow = lane & 15;
    const int lcol = (lane >> 4) * 4;

    const int nkt = K / GBK;

    // ---- prefetch tile 0 ----
    sa0 = *(const float4*)(A + (size_t)(m0 + ar)      * K + ac4 * 4);
    sa1 = *(const float4*)(A + (size_t)(m0 + ar + 64) * K + ac4 * 4);
    sb0 = *(const float4*)(B + (size_t)(bk)     * N + n0 + bn4 * 4);
    sb1 = *(const float4*)(B + (size_t)(bk + 8) * N + n0 + bn4 * 4);
    {
        float4 t;
        t.x = f2tf32(sa0.x); t.y = f2tf32(sa0.y); t.z = f2tf32(sa0.z); t.w = f2tf32(sa0.w);
        *(float4*)(&As[0][ar][ac4 * 4]) = t;
        t.x = f2tf32(sa1.x); t.y = f2tf32(sa1.y); t.z = f2tf32(sa1.z); t.w = f2tf32(sa1.w);
        *(float4*)(&As[0][ar + 64][ac4 * 4]) = t;
        t.x = f2tf32(sb0.x); t.y = f2tf32(sb0.y); t.z = f2tf32(sb0.z); t.w = f2tf32(sb0.w);
        *(float4*)(&Bs[0][bk][bn4 * 4]) = t;
        t.x = f2tf32(sb1.x); t.y = f2tf32(sb1.y); t.z = f2tf32(sb1.z); t.w = f2tf32(sb1.w);
        *(float4*)(&Bs[0][bk + 8][bn4 * 4]) = t;
    }
    __syncthreads();

    for (int kt = 0; kt < nkt; kt++) {
        const int cur = kt & 1;
        // issue next-tile global loads (latency hidden by compute below)
        if (kt + 1 < nkt) {
            const float* Ap = A + (size_t)(kt + 1) * GBK;
            const float* Bp = B + (size_t)((kt + 1) * GBK) * N;
            sa0 = *(const float4*)(Ap + (size_t)(m0 + ar)      * K + ac4 * 4);
            sa1 = *(const float4*)(Ap + (size_t)(m0 + ar + 64) * K + ac4 * 4);
            sb0 = *(const float4*)(Bp + (size_t)(bk)     * N + n0 + bn4 * 4);
            sb1 = *(const float4*)(Bp + (size_t)(bk + 8) * N + n0 + bn4 * 4);
        }

        // ---- compute on buffer 'cur' ----
#pragma unroll
        for (int kk = 0; kk < GBK; kk += 8) {
            uint32_t a[4][4];
#pragma unroll
            for (int mi = 0; mi < 4; mi++) {
                uint32_t addr = smem_u32(&As[cur][wm * 64 + mi * 16 + lrow][kk + lcol]);
                asm volatile("ldmatrix.sync.aligned.m8n8.x4.shared.b16 {%0,%1,%2,%3}, [%4];"
                             : "=r"(a[mi][0]), "=r"(a[mi][1]), "=r"(a[mi][2]), "=r"(a[mi][3])
                             : "r"(addr));
            }
            uint32_t b[4][2];
#pragma unroll
            for (int ni = 0; ni < 4; ni++) {
                int nc = wn * 32 + ni * 8 + (lane >> 2);
                b[ni][0] = __float_as_uint(Bs[cur][kk + (lane & 3)][nc]);
                b[ni][1] = __float_as_uint(Bs[cur][kk + 4 + (lane & 3)][nc]);
            }
#pragma unroll
            for (int mi = 0; mi < 4; mi++)
#pragma unroll
                for (int ni = 0; ni < 4; ni++) {
                    asm volatile(
                        "mma.sync.aligned.m16n8k8.row.col.f32.tf32.tf32.f32 "
                        "{%0,%1,%2,%3}, {%4,%5,%6,%7}, {%8,%9}, {%0,%1,%2,%3};"
                        : "+f"(acc[mi][ni][0]), "+f"(acc[mi][ni][1]),
                          "+f"(acc[mi][ni][2]), "+f"(acc[mi][ni][3])
                        : "r"(a[mi][0]), "r"(a[mi][1]), "r"(a[mi][2]), "r"(a[mi][3]),
                          "r"(b[ni][0]), "r"(b[ni][1]));
                }
        }

        // ---- store next tile into the other buffer ----
        if (kt + 1 < nkt) {
            const int nxt = cur ^ 1;
            float4 t;
            t.x = f2tf32(sa0.x); t.y = f2tf32(sa0.y); t.z = f2tf32(sa0.z); t.w = f2tf32(sa0.w);
            *(float4*)(&As[nxt][ar][ac4 * 4]) = t;
            t.x = f2tf32(sa1.x); t.y = f2tf32(sa1.y); t.z = f2tf32(sa1.z); t.w = f2tf32(sa1.w);
            *(float4*)(&As[nxt][ar + 64][ac4 * 4]) = t;
            t.x = f2tf32(sb0.x); t.y = f2tf32(sb0.y); t.z = f2tf32(sb0.z); t.w = f2tf32(sb0.w);
            *(float4*)(&Bs[nxt][bk][bn4 * 4]) = t;
            t.x = f2tf32(sb1.x); t.y = f2tf32(sb1.y); t.z = f2tf32(sb1.z); t.w = f2tf32(sb1.w);
            *(float4*)(&Bs[nxt][bk + 8][bn4 * 4]) = t;
        }
        __syncthreads();
    }

    // ---- epilogue ----
#pragma unroll
    for (int mi = 0; mi < 4; mi++) {
#pragma unroll
        for (int ni = 0; ni < 4; ni++) {
            int r = m0 + wm * 64 + mi * 16 + (lane >> 2);
            int c = n0 + wn * 32 + ni * 8 + (lane & 3) * 2;
            float2 v0 = make_float2(acc[mi][ni][0], acc[mi][ni][1]);
            float2 v1 = make_float2(acc[mi][ni][2], acc[mi][ni][3]);
            *(float2*)(C + (size_t)r * N + c)       = v0;
            *(float2*)(C + (size_t)(r + 8) * N + c) = v1;
        }
    }
}

// ---------------------------------------------------------------------------
// Causal flash attention, fp32 (unchanged from round 1 — passing).
// ---------------------------------------------------------------------------
#define BQ 64
#define BKK 32
#define NEG_BIG (-1e30f)

__global__ __launch_bounds__(256) void attn_kernel(const float* __restrict__ qkv,
                                                   float* __restrict__ y)
{
    __shared__ float QsT[HD][BQ + 4];    // [d][i]
    __shared__ float KsT[HD][BKK + 4];   // [d][j]
    __shared__ float Vs [BKK][HD];       // [j][d]
    __shared__ float PsT[BKK][BQ + 4];   // [j][i]

    const int tid = threadIdx.x;
    const int tx = tid & 15;
    const int ty = tid >> 4;
    const int i0 = ty * 4;
    const int j0 = tx * 2;
    const int d0 = tx * 4;

    const int qt = blockIdx.x;
    const int h  = blockIdx.y;
    const int b  = blockIdx.z;

    const size_t rowstride = 3 * EMB;
    const size_t qcol = (size_t)h * HD;
    const size_t kcol = EMB + (size_t)h * HD;
    const size_t vcol = 2 * EMB + (size_t)h * HD;
    const size_t batch_base = (size_t)b * SEQ;

#pragma unroll
    for (int it = 0; it < 4; it++) {
        int idx = tid + it * 256;
        int tl  = idx >> 4;
        int dv  = idx & 15;
        float4 q = *(const float4*)(qkv + (batch_base + qt*BQ + tl)*rowstride + qcol + dv*4);
        QsT[dv*4+0][tl] = q.x;
        QsT[dv*4+1][tl] = q.y;
        QsT[dv*4+2][tl] = q.z;
        QsT[dv*4+3][tl] = q.w;
    }

    float m[4], l[4], o[4][4];
#pragma unroll
    for (int i = 0; i < 4; i++) {
        m[i] = NEG_BIG; l[i] = 0.f;
#pragma unroll
        for (int d = 0; d < 4; d++) o[i][d] = 0.f;
    }

    const float scale = 0.125f;
    const int n_kt = 2*qt + 2;

    for (int kt = 0; kt < n_kt; kt++) {
        __syncthreads();
#pragma unroll
        for (int it = 0; it < 2; it++) {
            int idx = tid + it * 256;
            int tl  = idx >> 4;
            int dv  = idx & 15;
            const float* base = qkv + (batch_base + kt*BKK + tl)*rowstride;
            float4 kk = *(const float4*)(base + kcol + dv*4);
            KsT[dv*4+0][tl] = kk.x;
            KsT[dv*4+1][tl] = kk.y;
            KsT[dv*4+2][tl] = kk.z;
            KsT[dv*4+3][tl] = kk.w;
            *(float4*)(&Vs[tl][dv*4]) = *(const float4*)(base + vcol + dv*4);
        }
        __syncthreads();

        float s[4][2];
#pragma unroll
        for (int i = 0; i < 4; i++) { s[i][0] = 0.f; s[i][1] = 0.f; }
#pragma unroll 8
        for (int d = 0; d < HD; d++) {
            float4 qf = *(float4*)(&QsT[d][i0]);
            float2 kf = *(float2*)(&KsT[d][j0]);
            s[0][0] = fmaf(qf.x, kf.x, s[0][0]); s[0][1] = fmaf(qf.x, kf.y, s[0][1]);
            s[1][0] = fmaf(qf.y, kf.x, s[1][0]); s[1][1] = fmaf(qf.y, kf.y, s[1][1]);
            s[2][0] = fmaf(qf.z, kf.x, s[2][0]); s[2][1] = fmaf(qf.z, kf.y, s[2][1]);
            s[3][0] = fmaf(qf.w, kf.x, s[3][0]); s[3][1] = fmaf(qf.w, kf.y, s[3][1]);
        }

#pragma unroll
        for (int i = 0; i < 4; i++) {
            int ig = qt*BQ + i0 + i;
#pragma unroll
            for (int j = 0; j < 2; j++) {
                int jg = kt*BKK + j0 + j;
                s[i][j] = (jg <= ig) ? s[i][j] * scale : NEG_BIG;
            }
        }

        float alpha[4];
#pragma unroll
        for (int i = 0; i < 4; i++) {
            float mx = fmaxf(s[i][0], s[i][1]);
#pragma unroll
            for (int off = 1; off < 16; off <<= 1)
                mx = fmaxf(mx, __shfl_xor_sync(0xffffffffu, mx, off));
            float mn = fmaxf(m[i], mx);
            float p0 = __expf(s[i][0] - mn);
            float p1 = __expf(s[i][1] - mn);
            float rs = p0 + p1;
#pragma unroll
            for (int off = 1; off < 16; off <<= 1)
                rs += __shfl_xor_sync(0xffffffffu, rs, off);
            alpha[i] = __expf(m[i] - mn);
            l[i] = l[i] * alpha[i] + rs;
            m[i] = mn;
            PsT[j0+0][i0+i] = p0;
            PsT[j0+1][i0+i] = p1;
#pragma unroll
            for (int d = 0; d < 4; d++) o[i][d] *= alpha[i];
        }
        __syncthreads();

#pragma unroll 8
        for (int j = 0; j < BKK; j++) {
            float4 pf = *(float4*)(&PsT[j][i0]);
            float4 vf = *(float4*)(&Vs[j][d0]);
            o[0][0] = fmaf(pf.x, vf.x, o[0][0]); o[0][1] = fmaf(pf.x, vf.y, o[0][1]);
            o[0][2] = fmaf(pf.x, vf.z, o[0][2]); o[0][3] = fmaf(pf.x, vf.w, o[0][3]);
            o[1][0] = fmaf(pf.y, vf.x, o[1][0]); o[1][1] = fmaf(pf.y, vf.y, o[1][1]);
            o[1][2] = fmaf(pf.y, vf.z, o[1][2]); o[1][3] = fmaf(pf.y, vf.w, o[1][3]);
            o[2][0] = fmaf(pf.z, vf.x, o[2][0]); o[2][1] = fmaf(pf.z, vf.y, o[2][1]);
            o[2][2] = fmaf(pf.z, vf.z, o[2][2]); o[2][3] = fmaf(pf.z, vf.w, o[2][3]);
            o[3][0] = fmaf(pf.w, vf.x, o[3][0]); o[3][1] = fmaf(pf.w, vf.y, o[3][1]);
            o[3][2] = fmaf(pf.w, vf.z, o[3][2]); o[3][3] = fmaf(pf.w, vf.w, o[3][3]);
        }
    }

#pragma unroll
    for (int i = 0; i < 4; i++) {
        float inv = 1.0f / l[i];
        float4 v = make_float4(o[i][0]*inv, o[i][1]*inv, o[i][2]*inv, o[i][3]*inv);
        *(float4*)(y + (batch_base + qt*BQ + i0 + i)*(size_t)EMB + h*HD + d0) = v;
    }
}

// ---------------------------------------------------------------------------
extern "C" void kernel_launch(void* const* d_in, const int* in_sizes, int n_in,
                              void* d_out, int out_size)
{
    const float* x0     = (const float*)d_in[0];   // [4,2048,1024]
    const float* w_attn = (const float*)d_in[1];   // [1024,3072]
    const float* w_proj = (const float*)d_in[2];   // [1024,1024]
    float* out = (float*)d_out;                    // [4,2048,1024]

    void* p_qkv_v = nullptr;
    void* p_y_v   = nullptr;
    cudaGetSymbolAddress(&p_qkv_v, g_qkv);
    cudaGetSymbolAddress(&p_y_v,   g_y);
    float* p_qkv = (float*)p_qkv_v;
    float* p_y   = (float*)p_y_v;

    // 1) qkv = x0 @ w_attn        [8192,1024] x [1024,3072]
    gemm_tc<<<dim3(QKV_N/128, M_ROWS/128), 256>>>(x0, w_attn, p_qkv,
                                                  M_ROWS, QKV_N, EMB);
    // 2) flash attention          -> y [8192,1024]
    attn_kernel<<<dim3(SEQ/BQ, NH, BATCH), 256>>>(p_qkv, p_y);
    // 3) out = y @ w_proj         [8192,1024] x [1024,1024]
    gemm_tc<<<dim3(EMB/128, M_ROWS/128), 256>>>(p_y, w_proj, out,
                                                M_ROWS, EMB, EMB);
}

// round 4
// speedup vs baseline: 2.9089x; 1.8755x over previous
#include <cuda_runtime.h>
#include <cuda_bf16.h>
#include <math.h>
#include <stdint.h>

// Problem constants
#define BATCH 4
#define SEQ   2048
#define EMB   1024
#define NH    16
#define HD    64
#define M_ROWS (BATCH*SEQ)        // 8192
#define QKV_N  (3*EMB)            // 3072

// Scratch (device globals: allocation-free)
__device__ float g_qkv[(size_t)M_ROWS * QKV_N];   // [B*T, 3C]
__device__ float g_y  [(size_t)M_ROWS * EMB];     // [B*T, C]

__device__ __forceinline__ float f2tf32(float x) {
    float y;
    asm("cvt.rna.tf32.f32 %0, %1;" : "=f"(y) : "f"(x));
    return y;
}
__device__ __forceinline__ uint32_t smem_u32(const void* p) {
    return (uint32_t)__cvta_generic_to_shared(p);
}
__device__ __forceinline__ void mma_tf32(float* c, const uint32_t* a,
                                         uint32_t b0, uint32_t b1) {
    asm volatile(
        "mma.sync.aligned.m16n8k8.row.col.f32.tf32.tf32.f32 "
        "{%0,%1,%2,%3}, {%4,%5,%6,%7}, {%8,%9}, {%0,%1,%2,%3};"
        : "+f"(c[0]), "+f"(c[1]), "+f"(c[2]), "+f"(c[3])
        : "r"(a[0]), "r"(a[1]), "r"(a[2]), "r"(a[3]), "r"(b0), "r"(b1));
}

// ---------------------------------------------------------------------------
// TF32 tensor-core GEMM (unchanged from round 2, passing @125 TF/s)
// ---------------------------------------------------------------------------
#define GBK 16

__global__ __launch_bounds__(256) void gemm_tc(const float* __restrict__ A,
                                               const float* __restrict__ B,
                                               float* __restrict__ C,
                                               int M, int N, int K)
{
    __shared__ float As[2][128][20];
    __shared__ float Bs[2][GBK][132];

    const int tid  = threadIdx.x;
    const int lane = tid & 31;
    const int wid  = tid >> 5;
    const int wm   = wid >> 2;
    const int wn   = wid & 3;
    const int m0   = blockIdx.y * 128;
    const int n0   = blockIdx.x * 128;

    const int ar  = tid >> 2;
    const int ac4 = tid & 3;
    const int bk  = tid >> 5;
    const int bn4 = tid & 31;

    float acc[4][4][4];
#pragma unroll
    for (int i = 0; i < 4; i++)
#pragma unroll
        for (int j = 0; j < 4; j++)
#pragma unroll
            for (int r = 0; r < 4; r++) acc[i][j][r] = 0.f;

    float4 sa0, sa1, sb0, sb1;
    const int lrow = lane & 15;
    const int lcol = (lane >> 4) * 4;
    const int nkt = K / GBK;

    sa0 = *(const float4*)(A + (size_t)(m0 + ar)      * K + ac4 * 4);
    sa1 = *(const float4*)(A + (size_t)(m0 + ar + 64) * K + ac4 * 4);
    sb0 = *(const float4*)(B + (size_t)(bk)     * N + n0 + bn4 * 4);
    sb1 = *(const float4*)(B + (size_t)(bk + 8) * N + n0 + bn4 * 4);
    {
        float4 t;
        t.x = f2tf32(sa0.x); t.y = f2tf32(sa0.y); t.z = f2tf32(sa0.z); t.w = f2tf32(sa0.w);
        *(float4*)(&As[0][ar][ac4 * 4]) = t;
        t.x = f2tf32(sa1.x); t.y = f2tf32(sa1.y); t.z = f2tf32(sa1.z); t.w = f2tf32(sa1.w);
        *(float4*)(&As[0][ar + 64][ac4 * 4]) = t;
        t.x = f2tf32(sb0.x); t.y = f2tf32(sb0.y); t.z = f2tf32(sb0.z); t.w = f2tf32(sb0.w);
        *(float4*)(&Bs[0][bk][bn4 * 4]) = t;
        t.x = f2tf32(sb1.x); t.y = f2tf32(sb1.y); t.z = f2tf32(sb1.z); t.w = f2tf32(sb1.w);
        *(float4*)(&Bs[0][bk + 8][bn4 * 4]) = t;
    }
    __syncthreads();

    for (int kt = 0; kt < nkt; kt++) {
        const int cur = kt & 1;
        if (kt + 1 < nkt) {
            const float* Ap = A + (size_t)(kt + 1) * GBK;
            const float* Bp = B + (size_t)((kt + 1) * GBK) * N;
            sa0 = *(const float4*)(Ap + (size_t)(m0 + ar)      * K + ac4 * 4);
            sa1 = *(const float4*)(Ap + (size_t)(m0 + ar + 64) * K + ac4 * 4);
            sb0 = *(const float4*)(Bp + (size_t)(bk)     * N + n0 + bn4 * 4);
            sb1 = *(const float4*)(Bp + (size_t)(bk + 8) * N + n0 + bn4 * 4);
        }

#pragma unroll
        for (int kk = 0; kk < GBK; kk += 8) {
            uint32_t a[4][4];
#pragma unroll
            for (int mi = 0; mi < 4; mi++) {
                uint32_t addr = smem_u32(&As[cur][wm * 64 + mi * 16 + lrow][kk + lcol]);
                asm volatile("ldmatrix.sync.aligned.m8n8.x4.shared.b16 {%0,%1,%2,%3}, [%4];"
                             : "=r"(a[mi][0]), "=r"(a[mi][1]), "=r"(a[mi][2]), "=r"(a[mi][3])
                             : "r"(addr));
            }
            uint32_t b[4][2];
#pragma unroll
            for (int ni = 0; ni < 4; ni++) {
                int nc = wn * 32 + ni * 8 + (lane >> 2);
                b[ni][0] = __float_as_uint(Bs[cur][kk + (lane & 3)][nc]);
                b[ni][1] = __float_as_uint(Bs[cur][kk + 4 + (lane & 3)][nc]);
            }
#pragma unroll
            for (int mi = 0; mi < 4; mi++)
#pragma unroll
                for (int ni = 0; ni < 4; ni++)
                    mma_tf32(acc[mi][ni], a[mi], b[ni][0], b[ni][1]);
        }

        if (kt + 1 < nkt) {
            const int nxt = cur ^ 1;
            float4 t;
            t.x = f2tf32(sa0.x); t.y = f2tf32(sa0.y); t.z = f2tf32(sa0.z); t.w = f2tf32(sa0.w);
            *(float4*)(&As[nxt][ar][ac4 * 4]) = t;
            t.x = f2tf32(sa1.x); t.y = f2tf32(sa1.y); t.z = f2tf32(sa1.z); t.w = f2tf32(sa1.w);
            *(float4*)(&As[nxt][ar + 64][ac4 * 4]) = t;
            t.x = f2tf32(sb0.x); t.y = f2tf32(sb0.y); t.z = f2tf32(sb0.z); t.w = f2tf32(sb0.w);
            *(float4*)(&Bs[nxt][bk][bn4 * 4]) = t;
            t.x = f2tf32(sb1.x); t.y = f2tf32(sb1.y); t.z = f2tf32(sb1.z); t.w = f2tf32(sb1.w);
            *(float4*)(&Bs[nxt][bk + 8][bn4 * 4]) = t;
        }
        __syncthreads();
    }

#pragma unroll
    for (int mi = 0; mi < 4; mi++) {
#pragma unroll
        for (int ni = 0; ni < 4; ni++) {
            int r = m0 + wm * 64 + mi * 16 + (lane >> 2);
            int c = n0 + wn * 32 + ni * 8 + (lane & 3) * 2;
            *(float2*)(C + (size_t)r * N + c)       = make_float2(acc[mi][ni][0], acc[mi][ni][1]);
            *(float2*)(C + (size_t)(r + 8) * N + c) = make_float2(acc[mi][ni][2], acc[mi][ni][3]);
        }
    }
}

// ---------------------------------------------------------------------------
// Tensor-core causal flash attention (tf32 mma, fp32 accum).
// CTA = (b, h, 128-q tile). 8 warps, warp owns 16 q rows. BK=64 key tiles.
// ---------------------------------------------------------------------------
#define ATT_BQ 128
#define ATT_BK 64
#define ROWW   (HD + 4)                 // 68 floats, padded row

// smem float offsets
#define OFF_Q 0                          // [128][68]
#define OFF_K (128*ROWW)                 // [64][68]
#define OFF_V (OFF_K + 64*ROWW)          // [64][68]
#define OFF_P (OFF_V + 64*ROWW)          // 8 warps x [16][68]
#define ATT_SMEM_BYTES ((OFF_P + 8*16*ROWW) * 4)   // 104448

__global__ __launch_bounds__(256, 2) void attn_tc(const float* __restrict__ qkv,
                                                  float* __restrict__ y)
{
    extern __shared__ float sm[];
    float* Qs = sm + OFF_Q;
    float* Ks = sm + OFF_K;
    float* Vs = sm + OFF_V;

    const int tid  = threadIdx.x;
    const int lane = tid & 31;
    const int wid  = tid >> 5;
    const int gid  = lane >> 2;     // 0..7
    const int tig  = lane & 3;      // 0..3

    const int qt = blockIdx.x;      // 0..15
    const int h  = blockIdx.y;
    const int b  = blockIdx.z;

    const size_t rowstride = 3 * EMB;
    const size_t qcol = (size_t)h * HD;
    const size_t kcol = EMB + (size_t)h * HD;
    const size_t vcol = 2 * EMB + (size_t)h * HD;
    const size_t bbase = (size_t)b * SEQ;

    // ---- stage Q (scale folded, tf32-rounded) ----
    const float scale = 0.125f;     // 1/sqrt(64)
#pragma unroll
    for (int it = 0; it < 8; it++) {
        int idx = tid + it * 256;          // 2048 float4 slots
        int r   = idx >> 4;                // 0..127
        int dv  = idx & 15;
        float4 q = *(const float4*)(qkv + (bbase + qt*ATT_BQ + r)*rowstride + qcol + dv*4);
        float* dst = Qs + r*ROWW + dv*4;
        dst[0] = f2tf32(q.x*scale); dst[1] = f2tf32(q.y*scale);
        dst[2] = f2tf32(q.z*scale); dst[3] = f2tf32(q.w*scale);
    }

    float m0 = -1e30f, m1 = -1e30f, l0 = 0.f, l1 = 0.f;
    float o[8][4];
#pragma unroll
    for (int nt = 0; nt < 8; nt++)
#pragma unroll
        for (int c = 0; c < 4; c++) o[nt][c] = 0.f;

    float* Pw = sm + OFF_P + wid*16*ROWW;     // warp-private P stripe
    const int wrow0 = qt*ATT_BQ + wid*16;     // global q row of gid==0,half 0
    const int n_kt = 2*qt + 2;

    for (int kt = 0; kt < n_kt; kt++) {
        __syncthreads();    // all warps done with previous Ks/Vs
        // ---- stage K,V tile (tf32): 64 rows x 16 float4 = 1024 slots ----
#pragma unroll
        for (int it = 0; it < 4; it++) {
            int idx = tid + it * 256;          // 0..1023
            int r   = idx >> 4;                // 0..63
            int dv  = idx & 15;
            const float* base = qkv + (bbase + kt*ATT_BK + r)*rowstride;
            float4 kk = *(const float4*)(base + kcol + dv*4);
            float4 vv = *(const float4*)(base + vcol + dv*4);
            float* kd = Ks + r*ROWW + dv*4;
            kd[0]=f2tf32(kk.x); kd[1]=f2tf32(kk.y); kd[2]=f2tf32(kk.z); kd[3]=f2tf32(kk.w);
            float* vd = Vs + r*ROWW + dv*4;
            vd[0]=f2tf32(vv.x); vd[1]=f2tf32(vv.y); vd[2]=f2tf32(vv.z); vd[3]=f2tf32(vv.w);
        }
        __syncthreads();

        // ---- S = Q @ K^T  (warp: 16 x 64) ----
        float s[8][4];
#pragma unroll
        for (int nt = 0; nt < 8; nt++)
#pragma unroll
            for (int c = 0; c < 4; c++) s[nt][c] = 0.f;

#pragma unroll
        for (int kc = 0; kc < 8; kc++) {
            uint32_t qa[4];
            const float* qb = Qs + (wid*16 + gid)*ROWW + kc*8 + tig;
            qa[0] = __float_as_uint(qb[0]);
            qa[1] = __float_as_uint(qb[8*ROWW]);
            qa[2] = __float_as_uint(qb[4]);
            qa[3] = __float_as_uint(qb[8*ROWW + 4]);
#pragma unroll
            for (int nt = 0; nt < 8; nt++) {
                const float* kb = Ks + (nt*8 + gid)*ROWW + kc*8 + tig;
                mma_tf32(s[nt], qa, __float_as_uint(kb[0]), __float_as_uint(kb[4]));
            }
        }

        // ---- causal mask (only diagonal tiles) ----
        if (kt >= 2*qt) {
            const int col0 = kt*ATT_BK;
#pragma unroll
            for (int nt = 0; nt < 8; nt++) {
                int cbase = col0 + nt*8 + tig*2;
                int r0 = wrow0 + gid;
                if (cbase     > r0)     s[nt][0] = -1e30f;
                if (cbase + 1 > r0)     s[nt][1] = -1e30f;
                if (cbase     > r0 + 8) s[nt][2] = -1e30f;
                if (cbase + 1 > r0 + 8) s[nt][3] = -1e30f;
            }
        }

        // ---- online softmax (register-resident; row = 4-lane quad) ----
        float mx0 = -1e30f, mx1 = -1e30f;
#pragma unroll
        for (int nt = 0; nt < 8; nt++) {
            mx0 = fmaxf(mx0, fmaxf(s[nt][0], s[nt][1]));
            mx1 = fmaxf(mx1, fmaxf(s[nt][2], s[nt][3]));
        }
        mx0 = fmaxf(mx0, __shfl_xor_sync(0xffffffffu, mx0, 1));
        mx0 = fmaxf(mx0, __shfl_xor_sync(0xffffffffu, mx0, 2));
        mx1 = fmaxf(mx1, __shfl_xor_sync(0xffffffffu, mx1, 1));
        mx1 = fmaxf(mx1, __shfl_xor_sync(0xffffffffu, mx1, 2));
        float mn0 = fmaxf(m0, mx0);
        float mn1 = fmaxf(m1, mx1);
        float alpha0 = __expf(m0 - mn0);
        float alpha1 = __expf(m1 - mn1);
        float sum0 = 0.f, sum1 = 0.f;
#pragma unroll
        for (int nt = 0; nt < 8; nt++) {
            float p00 = __expf(s[nt][0] - mn0);
            float p01 = __expf(s[nt][1] - mn0);
            float p10 = __expf(s[nt][2] - mn1);
            float p11 = __expf(s[nt][3] - mn1);
            sum0 += p00 + p01;
            sum1 += p10 + p11;
            *(float2*)(Pw + gid*ROWW       + nt*8 + tig*2) = make_float2(f2tf32(p00), f2tf32(p01));
            *(float2*)(Pw + (gid+8)*ROWW   + nt*8 + tig*2) = make_float2(f2tf32(p10), f2tf32(p11));
            o[nt][0] *= alpha0; o[nt][1] *= alpha0;
            o[nt][2] *= alpha1; o[nt][3] *= alpha1;
        }
        sum0 += __shfl_xor_sync(0xffffffffu, sum0, 1);
        sum0 += __shfl_xor_sync(0xffffffffu, sum0, 2);
        sum1 += __shfl_xor_sync(0xffffffffu, sum1, 1);
        sum1 += __shfl_xor_sync(0xffffffffu, sum1, 2);
        l0 = l0*alpha0 + sum0;
        l1 = l1*alpha1 + sum1;
        m0 = mn0; m1 = mn1;
        __syncwarp();

        // ---- O += P @ V  (warp-private P, shared V) ----
#pragma unroll
        for (int kc = 0; kc < 8; kc++) {
            uint32_t pa[4];
            const float* pb = Pw + gid*ROWW + kc*8 + tig;
            pa[0] = __float_as_uint(pb[0]);
            pa[1] = __float_as_uint(pb[8*ROWW]);
            pa[2] = __float_as_uint(pb[4]);
            pa[3] = __float_as_uint(pb[8*ROWW + 4]);
#pragma unroll
            for (int nt = 0; nt < 8; nt++) {
                const float* vb = Vs + (kc*8 + tig)*ROWW + nt*8 + gid;
                mma_tf32(o[nt], pa, __float_as_uint(vb[0]), __float_as_uint(vb[4*ROWW]));
            }
        }
        __syncwarp();   // P stripe reads done before next-iter overwrite
    }

    // ---- epilogue ----
    float inv0 = 1.0f / l0;
    float inv1 = 1.0f / l1;
    const size_t r0 = bbase + wrow0 + gid;
#pragma unroll
    for (int nt = 0; nt < 8; nt++) {
        *(float2*)(y + r0*EMB       + h*HD + nt*8 + tig*2) = make_float2(o[nt][0]*inv0, o[nt][1]*inv0);
        *(float2*)(y + (r0+8)*EMB   + h*HD + nt*8 + tig*2) = make_float2(o[nt][2]*inv1, o[nt][3]*inv1);
    }
}

// ---------------------------------------------------------------------------
extern "C" void kernel_launch(void* const* d_in, const int* in_sizes, int n_in,
                              void* d_out, int out_size)
{
    const float* x0     = (const float*)d_in[0];   // [4,2048,1024]
    const float* w_attn = (const float*)d_in[1];   // [1024,3072]
    const float* w_proj = (const float*)d_in[2];   // [1024,1024]
    float* out = (float*)d_out;                    // [4,2048,1024]

    void* p_qkv_v = nullptr;
    void* p_y_v   = nullptr;
    cudaGetSymbolAddress(&p_qkv_v, g_qkv);
    cudaGetSymbolAddress(&p_y_v,   g_y);
    float* p_qkv = (float*)p_qkv_v;
    float* p_y   = (float*)p_y_v;

    cudaFuncSetAttribute(attn_tc, cudaFuncAttributeMaxDynamicSharedMemorySize,
                         ATT_SMEM_BYTES);

    // 1) qkv = x0 @ w_attn
    gemm_tc<<<dim3(QKV_N/128, M_ROWS/128), 256>>>(x0, w_attn, p_qkv,
                                                  M_ROWS, QKV_N, EMB);
    // 2) flash attention (tensor cores)
    attn_tc<<<dim3(SEQ/ATT_BQ, NH, BATCH), 256, ATT_SMEM_BYTES>>>(p_qkv, p_y);
    // 3) out = y @ w_proj
    gemm_tc<<<dim3(EMB/128, M_ROWS/128), 256>>>(p_y, w_proj, out,
                                                M_ROWS, EMB, EMB);
}